// round 5
// baseline (speedup 1.0000x reference)
#include <cuda_runtime.h>
#include <cuda_bf16.h>
#include <math.h>
#include <stdint.h>

// Problem constants: B=8, T=4096, C=1024, H=1024
#define BB 8
#define TT 4096
#define CC 1024
#define HH 1024

typedef __nv_bfloat16 bf16;

// ---------------------------------------------------------------------------
// Static device scratch (no allocation allowed).
// ---------------------------------------------------------------------------
__device__ bf16 g_xh[(size_t)BB * TT * CC];
__device__ bf16 g_xl[(size_t)BB * TT * CC];
__device__ bf16 g_wqh[HH * CC], g_wql[HH * CC];
__device__ bf16 g_wkh[HH * CC], g_wkl[HH * CC];
__device__ bf16 g_wvh[HH * CC], g_wvl[HH * CC];
__device__ bf16 g_qh[(size_t)BB * TT * HH], g_ql[(size_t)BB * TT * HH];
__device__ bf16 g_kh[(size_t)BB * TT * HH], g_kl[(size_t)BB * TT * HH];
__device__ bf16 g_vh[(size_t)BB * TT * HH], g_vl[(size_t)BB * TT * HH];
// V transposed per batch: [b][h][t]
__device__ bf16 g_vth[(size_t)BB * HH * TT], g_vtl[(size_t)BB * HH * TT];
__device__ float g_s[(size_t)BB * TT * TT];
__device__ bf16 g_ph[(size_t)BB * TT * TT], g_pl[(size_t)BB * TT * TT];

// ---------------------------------------------------------------------------
// helpers
// ---------------------------------------------------------------------------
__device__ __forceinline__ uint32_t smem_u32(const void* p) {
    uint32_t a;
    asm("{ .reg .u64 t; cvta.to.shared.u64 t, %1; cvt.u32.u64 %0, t; }"
        : "=r"(a) : "l"(p));
    return a;
}
__device__ __forceinline__ void cp_async16(uint32_t s, const void* g) {
    asm volatile("cp.async.cg.shared.global [%0], [%1], 16;" :: "r"(s), "l"(g));
}
#define CP_COMMIT() asm volatile("cp.async.commit_group;" ::: "memory")
#define CP_WAIT1()  asm volatile("cp.async.wait_group 1;" ::: "memory")

// m16n8k16 bf16 MMA (base ISA)
__device__ __forceinline__ void mma16816(float* c, const uint32_t* a,
                                         uint32_t b0, uint32_t b1)
{
    asm volatile(
        "mma.sync.aligned.m16n8k16.row.col.f32.bf16.bf16.f32 "
        "{%0,%1,%2,%3}, {%4,%5,%6,%7}, {%8,%9}, {%0,%1,%2,%3};"
        : "+f"(c[0]), "+f"(c[1]), "+f"(c[2]), "+f"(c[3])
        : "r"(a[0]), "r"(a[1]), "r"(a[2]), "r"(a[3]), "r"(b0), "r"(b1));
}

__device__ __forceinline__ void ldsm_x4(uint32_t& r0, uint32_t& r1,
                                        uint32_t& r2, uint32_t& r3, uint32_t a)
{
    asm volatile("ldmatrix.sync.aligned.m8n8.x4.shared.b16 {%0,%1,%2,%3}, [%4];"
                 : "=r"(r0), "=r"(r1), "=r"(r2), "=r"(r3) : "r"(a));
}

// ---------------------------------------------------------------------------
// bf16x3 NT GEMM:  D[M,N] = alpha * (A[M,K] @ B[N,K]^T)
// A,B as (hi,lo) bf16 pairs; D = Ah*Bh + Ah*Bl + Al*Bh in fp32 accum.
// CTA tile 128x128x32.  256 threads = 8 warps (4M x 2N), warp tile 32x64.
// cp.async double-buffered smem (2 stages x 40960 B), 2 CTAs/SM.
// Fragments via ldmatrix.x4 (conflict-free on 80 B padded rows).
// EPI: 0 = fp32*alpha -> outF ;  1 = hi/lo bf16 -> outH/outL (row-major).
// ---------------------------------------------------------------------------
constexpr int STAGE = 40960;                 // 4 tiles x 128 rows x 80 B
constexpr int T_AH = 0, T_AL = 10240, T_BH = 20480, T_BL = 30720;

template <int EPI>
__global__ __launch_bounds__(256, 2) void gemm_mma_kernel(
    const bf16* __restrict__ Ah, const bf16* __restrict__ Al,
    const bf16* __restrict__ Bh, const bf16* __restrict__ Bl,
    float* __restrict__ outF, bf16* __restrict__ outH, bf16* __restrict__ outL,
    int M, int N, int K,
    long long sA, long long sB, long long sC, float alpha)
{
    extern __shared__ __align__(16) unsigned char sm[];
    const uint32_t sbase = smem_u32(sm);

    const int tid = threadIdx.x;
    const int wid = tid >> 5;
    const int lane = tid & 31;
    const int g = lane >> 2;      // row-in-frag group (epilogue)
    const int t = lane & 3;       // col pair (epilogue)
    const int wm = wid & 3;       // warp M (0..3) -> rows wm*32
    const int wn = wid >> 2;      // warp N (0..1) -> cols wn*64

    const long long bz = blockIdx.z;
    Ah += bz * sA;  Al += bz * sA;
    Bh += bz * sB;  Bl += bz * sB;

    const int bm = blockIdx.y * 128;
    const int bn = blockIdx.x * 128;
    const int nk = K >> 5;        // K / 32

    // loader mapping: 512 uint4 slots/tile; thread owns slots tid, tid+256
    const int lrow = tid >> 2;          // 0..63 (+64 second slot)
    const int lc4  = tid & 3;
    const uint32_t so0 = (uint32_t)(lrow * 80 + lc4 * 16);
    const uint32_t so1 = so0 + 64u * 80u;

    // ldmatrix per-lane offsets (within a stage)
    // A (row-major 16x16 frag): row = base + (lane&15), chunk = (lane>>4)*16
    const uint32_t aoff0 = (uint32_t)((wm * 32 + 0  + (lane & 15)) * 80 + ((lane >> 4) * 16));
    const uint32_t aoff1 = (uint32_t)((wm * 32 + 16 + (lane & 15)) * 80 + ((lane >> 4) * 16));
    // B (n-major, k16 x n16 per ldsm.x4): row = base + ((lane>>4)<<3) + (lane&7),
    // chunk = ((lane>>3)&1)*16
    uint32_t boff[4];
    #pragma unroll
    for (int ntp = 0; ntp < 4; ntp++)
        boff[ntp] = (uint32_t)((wn * 64 + ntp * 16 + ((lane >> 4) << 3) + (lane & 7)) * 80
                               + (((lane >> 3) & 1) * 16));

    auto issue_stage = [&](int kt, int buf) {
        const uint32_t st = sbase + (uint32_t)buf * STAGE;
        const size_t ka = (size_t)kt * 32 + lc4 * 8;
        const size_t a0 = (size_t)(bm + lrow) * K + ka;
        const size_t a1 = (size_t)(bm + lrow + 64) * K + ka;
        const size_t b0 = (size_t)(bn + lrow) * K + ka;
        const size_t b1 = (size_t)(bn + lrow + 64) * K + ka;
        cp_async16(st + T_AH + so0, Ah + a0);
        cp_async16(st + T_AH + so1, Ah + a1);
        cp_async16(st + T_AL + so0, Al + a0);
        cp_async16(st + T_AL + so1, Al + a1);
        cp_async16(st + T_BH + so0, Bh + b0);
        cp_async16(st + T_BH + so1, Bh + b1);
        cp_async16(st + T_BL + so0, Bl + b0);
        cp_async16(st + T_BL + so1, Bl + b1);
    };

    float acc[2][8][4];
    #pragma unroll
    for (int mt = 0; mt < 2; mt++)
        #pragma unroll
        for (int nt = 0; nt < 8; nt++)
            #pragma unroll
            for (int i = 0; i < 4; i++) acc[mt][nt][i] = 0.0f;

    issue_stage(0, 0);
    CP_COMMIT();

    for (int kt = 0; kt < nk; kt++) {
        if (kt + 1 < nk) issue_stage(kt + 1, (kt + 1) & 1);
        CP_COMMIT();
        CP_WAIT1();
        __syncthreads();

        const uint32_t stg = sbase + (uint32_t)(kt & 1) * STAGE;

        #pragma unroll
        for (int ks = 0; ks < 2; ks++) {
            const uint32_t kso = (uint32_t)(ks * 32);
            uint32_t ah[2][4], al[2][4];
            ldsm_x4(ah[0][0], ah[0][1], ah[0][2], ah[0][3], stg + T_AH + aoff0 + kso);
            ldsm_x4(ah[1][0], ah[1][1], ah[1][2], ah[1][3], stg + T_AH + aoff1 + kso);
            ldsm_x4(al[0][0], al[0][1], al[0][2], al[0][3], stg + T_AL + aoff0 + kso);
            ldsm_x4(al[1][0], al[1][1], al[1][2], al[1][3], stg + T_AL + aoff1 + kso);
            #pragma unroll
            for (int ntp = 0; ntp < 4; ntp++) {
                uint32_t bh[4], bl[4];
                ldsm_x4(bh[0], bh[1], bh[2], bh[3], stg + T_BH + boff[ntp] + kso);
                ldsm_x4(bl[0], bl[1], bl[2], bl[3], stg + T_BL + boff[ntp] + kso);
                #pragma unroll
                for (int mt = 0; mt < 2; mt++) {
                    mma16816(acc[mt][2 * ntp],     ah[mt], bh[0], bh[1]);
                    mma16816(acc[mt][2 * ntp],     ah[mt], bl[0], bl[1]);
                    mma16816(acc[mt][2 * ntp],     al[mt], bh[0], bh[1]);
                    mma16816(acc[mt][2 * ntp + 1], ah[mt], bh[2], bh[3]);
                    mma16816(acc[mt][2 * ntp + 1], ah[mt], bl[2], bl[3]);
                    mma16816(acc[mt][2 * ntp + 1], al[mt], bh[2], bh[3]);
                }
            }
        }
        __syncthreads();
    }

    // ---- epilogue ----
    #pragma unroll
    for (int mt = 0; mt < 2; mt++) {
        const int r0 = bm + wm * 32 + mt * 16 + g;
        #pragma unroll
        for (int nt = 0; nt < 8; nt++) {
            const int c0 = bn + wn * 64 + nt * 8 + 2 * t;
            if (EPI == 0) {
                float2 v0, v1;
                v0.x = alpha * acc[mt][nt][0]; v0.y = alpha * acc[mt][nt][1];
                v1.x = alpha * acc[mt][nt][2]; v1.y = alpha * acc[mt][nt][3];
                *reinterpret_cast<float2*>(outF + bz * sC + (size_t)r0 * N + c0) = v0;
                *reinterpret_cast<float2*>(outF + bz * sC + (size_t)(r0 + 8) * N + c0) = v1;
            } else {
                #pragma unroll
                for (int h = 0; h < 2; h++) {
                    const float v0 = acc[mt][nt][2 * h + 0];
                    const float v1 = acc[mt][nt][2 * h + 1];
                    bf16 h0 = __float2bfloat16(v0);
                    bf16 h1 = __float2bfloat16(v1);
                    bf16 l0 = __float2bfloat16(v0 - __bfloat162float(h0));
                    bf16 l1 = __float2bfloat16(v1 - __bfloat162float(h1));
                    __nv_bfloat162 hp; hp.x = h0; hp.y = h1;
                    __nv_bfloat162 lp; lp.x = l0; lp.y = l1;
                    const size_t off = (size_t)(r0 + 8 * h) * N + c0;
                    *reinterpret_cast<__nv_bfloat162*>(outH + off) = hp;
                    *reinterpret_cast<__nv_bfloat162*>(outL + off) = lp;
                }
            }
        }
    }
}

// ---------------------------------------------------------------------------
// fp32 -> (hi, lo) bf16 split, float4-vectorized.  n4 = n/4.
// ---------------------------------------------------------------------------
__global__ __launch_bounds__(256) void convert_hilo_kernel(
    const float4* __restrict__ in, __nv_bfloat162* __restrict__ h2,
    __nv_bfloat162* __restrict__ l2, long long n4)
{
    long long i = (long long)blockIdx.x * blockDim.x + threadIdx.x;
    if (i >= n4) return;
    float4 v = in[i];
    bf16 h0 = __float2bfloat16(v.x), h1 = __float2bfloat16(v.y);
    bf16 h2v = __float2bfloat16(v.z), h3 = __float2bfloat16(v.w);
    bf16 l0 = __float2bfloat16(v.x - __bfloat162float(h0));
    bf16 l1 = __float2bfloat16(v.y - __bfloat162float(h1));
    bf16 l2v = __float2bfloat16(v.z - __bfloat162float(h2v));
    bf16 l3 = __float2bfloat16(v.w - __bfloat162float(h3));
    __nv_bfloat162 a; a.x = h0; a.y = h1;
    __nv_bfloat162 b; b.x = h2v; b.y = h3;
    __nv_bfloat162 c; c.x = l0; c.y = l1;
    __nv_bfloat162 d; d.x = l2v; d.y = l3;
    h2[2 * i] = a; h2[2 * i + 1] = b;
    l2[2 * i] = c; l2[2 * i + 1] = d;
}

// ---------------------------------------------------------------------------
// Per-batch transpose of hi/lo V: out[b][h][t] = in[b][t][h]
// ---------------------------------------------------------------------------
__global__ __launch_bounds__(1024) void transpose_hilo_kernel(
    const bf16* __restrict__ ih, const bf16* __restrict__ il,
    bf16* __restrict__ oh, bf16* __restrict__ ol)
{
    __shared__ bf16 th[32][33];
    __shared__ bf16 tl[32][33];
    const int b = blockIdx.z;
    const int h0 = blockIdx.x * 32;
    const int t0 = blockIdx.y * 32;
    const int tx = threadIdx.x, ty = threadIdx.y;

    const size_t iin = ((size_t)b * TT + t0 + ty) * HH + h0 + tx;
    th[ty][tx] = ih[iin];
    tl[ty][tx] = il[iin];
    __syncthreads();
    const size_t iout = ((size_t)b * HH + h0 + ty) * TT + t0 + tx;
    oh[iout] = th[tx][ty];
    ol[iout] = tl[tx][ty];
}

// ---------------------------------------------------------------------------
// Row softmax over S (fp32, rows of TT) -> P as (hi, lo) bf16.
// ---------------------------------------------------------------------------
__global__ __launch_bounds__(256) void softmax_kernel(
    const float* __restrict__ S, bf16* __restrict__ Ph, bf16* __restrict__ Pl)
{
    __shared__ float buf[TT];
    __shared__ float red[256];
    const size_t row = blockIdx.x;
    const float4* p4 = reinterpret_cast<const float4*>(S + row * TT);
    const int tid = threadIdx.x;

    float m = -INFINITY;
    for (int i = tid; i < TT / 4; i += 256) {
        float4 v = p4[i];
        reinterpret_cast<float4*>(buf)[i] = v;
        m = fmaxf(m, fmaxf(fmaxf(v.x, v.y), fmaxf(v.z, v.w)));
    }
    red[tid] = m;
    __syncthreads();
    #pragma unroll
    for (int st = 128; st > 0; st >>= 1) {
        if (tid < st) red[tid] = fmaxf(red[tid], red[tid + st]);
        __syncthreads();
    }
    m = red[0];
    __syncthreads();

    float sum = 0.0f;
    for (int i = tid; i < TT; i += 256) {
        float e = __expf(buf[i] - m);
        buf[i] = e;
        sum += e;
    }
    red[tid] = sum;
    __syncthreads();
    #pragma unroll
    for (int st = 128; st > 0; st >>= 1) {
        if (tid < st) red[tid] += red[tid + st];
        __syncthreads();
    }
    const float inv = 1.0f / red[0];
    __syncthreads();

    __nv_bfloat162* ph2 = reinterpret_cast<__nv_bfloat162*>(Ph + row * TT);
    __nv_bfloat162* pl2 = reinterpret_cast<__nv_bfloat162*>(Pl + row * TT);
    for (int i = tid; i < TT / 2; i += 256) {
        float e0 = buf[2 * i] * inv;
        float e1 = buf[2 * i + 1] * inv;
        bf16 h0 = __float2bfloat16(e0), h1 = __float2bfloat16(e1);
        bf16 l0 = __float2bfloat16(e0 - __bfloat162float(h0));
        bf16 l1 = __float2bfloat16(e1 - __bfloat162float(h1));
        __nv_bfloat162 hp; hp.x = h0; hp.y = h1;
        __nv_bfloat162 lp; lp.x = l0; lp.y = l1;
        ph2[i] = hp;
        pl2[i] = lp;
    }
}

// ---------------------------------------------------------------------------
extern "C" void kernel_launch(void* const* d_in, const int* in_sizes, int n_in,
                              void* d_out, int out_size)
{
    const float* x  = (const float*)d_in[0];
    const float* Wq = (const float*)d_in[1];
    const float* Wk = (const float*)d_in[2];
    const float* Wv = (const float*)d_in[3];
    float* out = (float*)d_out;

    bf16 *xh, *xl, *wqh, *wql, *wkh, *wkl, *wvh, *wvl;
    bf16 *qh, *ql, *kh, *kl, *vh, *vl, *vth, *vtl, *phb, *plb;
    float* s;
    cudaGetSymbolAddress((void**)&xh, g_xh);   cudaGetSymbolAddress((void**)&xl, g_xl);
    cudaGetSymbolAddress((void**)&wqh, g_wqh); cudaGetSymbolAddress((void**)&wql, g_wql);
    cudaGetSymbolAddress((void**)&wkh, g_wkh); cudaGetSymbolAddress((void**)&wkl, g_wkl);
    cudaGetSymbolAddress((void**)&wvh, g_wvh); cudaGetSymbolAddress((void**)&wvl, g_wvl);
    cudaGetSymbolAddress((void**)&qh, g_qh);   cudaGetSymbolAddress((void**)&ql, g_ql);
    cudaGetSymbolAddress((void**)&kh, g_kh);   cudaGetSymbolAddress((void**)&kl, g_kl);
    cudaGetSymbolAddress((void**)&vh, g_vh);   cudaGetSymbolAddress((void**)&vl, g_vl);
    cudaGetSymbolAddress((void**)&vth, g_vth); cudaGetSymbolAddress((void**)&vtl, g_vtl);
    cudaGetSymbolAddress((void**)&s, g_s);
    cudaGetSymbolAddress((void**)&phb, g_ph);  cudaGetSymbolAddress((void**)&plb, g_pl);

    const int DSMEM = 2 * STAGE;   // 81920 B
    static bool attr_done = false;
    if (!attr_done) {
        cudaFuncSetAttribute(gemm_mma_kernel<0>,
                             cudaFuncAttributeMaxDynamicSharedMemorySize, DSMEM);
        cudaFuncSetAttribute(gemm_mma_kernel<1>,
                             cudaFuncAttributeMaxDynamicSharedMemorySize, DSMEM);
        attr_done = true;
    }

    // 1) hi/lo splits of inputs
    {
        long long n4 = (long long)BB * TT * CC / 4;
        convert_hilo_kernel<<<(unsigned)((n4 + 255) / 256), 256>>>(
            (const float4*)x, (__nv_bfloat162*)xh, (__nv_bfloat162*)xl, n4);
        long long w4 = (long long)HH * CC / 4;
        convert_hilo_kernel<<<(unsigned)((w4 + 255) / 256), 256>>>(
            (const float4*)Wq, (__nv_bfloat162*)wqh, (__nv_bfloat162*)wql, w4);
        convert_hilo_kernel<<<(unsigned)((w4 + 255) / 256), 256>>>(
            (const float4*)Wk, (__nv_bfloat162*)wkh, (__nv_bfloat162*)wkl, w4);
        convert_hilo_kernel<<<(unsigned)((w4 + 255) / 256), 256>>>(
            (const float4*)Wv, (__nv_bfloat162*)wvh, (__nv_bfloat162*)wvl, w4);
    }

    // 2) projections: [BB*TT, HH] = x @ W^T  (hi/lo outputs)
    {
        dim3 g(HH / 128, (BB * TT) / 128, 1);
        gemm_mma_kernel<1><<<g, 256, DSMEM>>>(xh, xl, wqh, wql, nullptr, qh, ql,
                                              BB * TT, HH, CC, 0, 0, 0, 1.0f);
        gemm_mma_kernel<1><<<g, 256, DSMEM>>>(xh, xl, wkh, wkl, nullptr, kh, kl,
                                              BB * TT, HH, CC, 0, 0, 0, 1.0f);
        gemm_mma_kernel<1><<<g, 256, DSMEM>>>(xh, xl, wvh, wvl, nullptr, vh, vl,
                                              BB * TT, HH, CC, 0, 0, 0, 1.0f);
    }

    // 3) transpose V per batch: vt[b][h][t] = v[b][t][h]
    {
        dim3 g(HH / 32, TT / 32, BB);
        transpose_hilo_kernel<<<g, dim3(32, 32, 1)>>>(vh, vl, vth, vtl);
    }

    // 4) scores: S_b = (Q_b @ K_b^T) / 32
    {
        dim3 g(TT / 128, TT / 128, BB);
        gemm_mma_kernel<0><<<g, 256, DSMEM>>>(qh, ql, kh, kl, s, nullptr, nullptr,
                                              TT, TT, HH,
                                              (long long)TT * HH, (long long)TT * HH,
                                              (long long)TT * TT, 1.0f / 32.0f);
    }

    // 5) softmax -> P hi/lo
    softmax_kernel<<<BB * TT, 256>>>(s, phb, plb);

    // 6) out_b = P_b @ V_b  (NT with vt[b][h][t])
    {
        dim3 g(HH / 128, TT / 128, BB);
        gemm_mma_kernel<0><<<g, 256, DSMEM>>>(phb, plb, vth, vtl, out, nullptr, nullptr,
                                              TT, HH, TT,
                                              (long long)TT * TT, (long long)HH * TT,
                                              (long long)TT * HH, 1.0f);
    }
}